// round 6
// baseline (speedup 1.0000x reference)
#include <cuda_runtime.h>
#include <cstdint>

typedef unsigned long long u64;
typedef unsigned int u32;

// Problem geometry
#define CB_K 512
#define CB_C 64
#define HW   4096
#define N_PIX 524288
#define Q_ELEMS 33554432
#define OFF_IDX  Q_ELEMS
#define OFF_LOSS (OFF_IDX + N_PIX)
#define OFF_ENT  (OFF_LOSS + 1)

#define MT 128
#define NTILES (N_PIX / MT)          // 4096
#define THREADS 256

#define FTS 136                      // fT stride (floats)
#define HS  36                       // half-pair stride in words (72 halves): (4*lg+lt) bank-perfect

// smem byte offsets
#define SB_FH   0                    // fh  [pix][ch] halves 128x72  = 18432
#define SB_EKH  18432                // ekh [code][ch] halves 512x72 = 73728
#define SB_FT   92160                // fT  [ch][pix] f32 64x136     = 34816
#define SB_EE   126976               // E_k 512 f32
#define SB_S    129024               // S[p] 128 f32
#define SB_W    129536               // w[p] 128 f32
#define SB_HIST 130048               // 512 int
#define SB_WIN  132096               // 128 u64 packed (d,k)
#define SB_LANE 133120               // 4 f32
#define SB_EMAX 133136               // 1 int
#define SMEM_TOTAL 133376

__device__ double g_lane[4];
__device__ int    g_counts[CB_K];

__global__ void vq_zero(){
    int t = threadIdx.x;
    if (t < CB_K) g_counts[t] = 0;
    if (t < 4)    g_lane[t] = 0.0;
}

__device__ __forceinline__ void mma_f16(float* d, const u32* a, const u32* b){
    asm volatile("mma.sync.aligned.m16n8k16.row.col.f32.f16.f16.f32 "
        "{%0,%1,%2,%3}, {%4,%5,%6,%7}, {%8,%9}, {%0,%1,%2,%3};"
        : "+f"(d[0]), "+f"(d[1]), "+f"(d[2]), "+f"(d[3])
        : "r"(a[0]), "r"(a[1]), "r"(a[2]), "r"(a[3]), "r"(b[0]), "r"(b[1]));
}
__device__ __forceinline__ u32 pack_h2(float lo, float hi){
    u32 h; asm("cvt.rn.f16x2.f32 %0, %1, %2;" : "=r"(h) : "f"(hi), "f"(lo));
    return h;
}

__global__ void __launch_bounds__(THREADS, 1)
vq_mma(const float* __restrict__ x, const float* __restrict__ cb, float* __restrict__ out)
{
    extern __shared__ char smem[];
    u32*   fh_w  = (u32*)(smem + SB_FH);
    u32*   ekh_w = (u32*)(smem + SB_EKH);
    float* fT    = (float*)(smem + SB_FT);
    float* ee    = (float*)(smem + SB_EE);
    float* Sarr  = (float*)(smem + SB_S);
    float* warr  = (float*)(smem + SB_W);
    int*   hist  = (int*)(smem + SB_HIST);
    u64*   win   = (u64*)(smem + SB_WIN);
    float* lane_sum = (float*)(smem + SB_LANE);
    int*   emax_i   = (int*)(smem + SB_EMAX);

    const int tid  = threadIdx.x;
    const int wid  = tid >> 5;
    const int lane = tid & 31;
    const int lg   = lane >> 2;
    const int lt   = lane & 3;

    const int tile = blockIdx.x;
    const int plane = tile >> 5;
    const int pixbase = (tile & 31) * MT;

    // ---- Staging ----
    // codebook -> halves (coalesced float2 LDG; conflict-free b32 STS)
    for (int i = tid; i < CB_K * 32; i += THREADS) {
        int k = i >> 5, c2 = i & 31;
        float2 v = *(const float2*)(cb + k * CB_C + 2 * c2);
        ekh_w[k * HS + c2] = pack_h2(v.x, v.y);
    }
    // x tile -> fT f32 (coalesced)
    const float* xin = x + (size_t)plane * (CB_C * HW) + pixbase;
    for (int i = tid; i < MT * CB_C / 4; i += THREADS) {
        int c = i >> 5, p4 = i & 31;
        float4 v = *(const float4*)(xin + (size_t)c * HW + 4 * p4);
        *(float4*)(fT + c * FTS + 4 * p4) = v;
    }
    for (int k = tid; k < CB_K; k += THREADS) hist[k] = 0;
    if (tid < MT) win[tid] = ~0ull;
    if (tid < 4)  lane_sum[tid] = 0.f;
    if (tid == 0) *emax_i = 0;
    __syncthreads();

    // fh halves from fT (transpose; rare staging conflicts acceptable)
    for (int i = tid; i < MT * 32; i += THREADS) {
        int p = i >> 5, c2 = i & 31;
        fh_w[p * HS + c2] = pack_h2(fT[(2 * c2) * FTS + p], fT[(2 * c2 + 1) * FTS + p]);
    }
    // E_k exact from global codebook (sequential fma ascending c), Emax
    for (int k = tid; k < CB_K; k += THREADS) {
        const float4* eg = (const float4*)(cb + k * CB_C);
        float s = 0.f;
        #pragma unroll
        for (int c4 = 0; c4 < 16; ++c4) {
            float4 e = __ldg(eg + c4);
            s = __fmaf_rn(e.x, e.x, s); s = __fmaf_rn(e.y, e.y, s);
            s = __fmaf_rn(e.z, e.z, s); s = __fmaf_rn(e.w, e.w, s);
        }
        ee[k] = s;
        atomicMax(emax_i, __float_as_int(s));
    }
    if (tid < MT) {
        float s = 0.f;
        #pragma unroll
        for (int c = 0; c < CB_C; ++c) { float v = fT[c * FTS + tid]; s = __fmaf_rn(v, v, s); }
        Sarr[tid] = s;
    }
    __syncthreads();
    if (tid < MT)   // |d'-d| <= 2^-9*sqrt(S*Emax)+2e-5; 2x margin
        warr[tid] = __fmaf_rn(0.00390625f, __fsqrt_rn(Sarr[tid] * __int_as_float(*emax_i)), 3e-5f);
    __syncthreads();

    // ---- f16 mma.sync prune + exact verify ----
    const int mbase = (wid >> 2) * 64;
    const int nq = wid & 3;

    #pragma unroll 1
    for (int pass = 0; pass < 2; ++pass) {
        const int nbase = pass * 256 + nq * 64;
        float D[4][8][4];
        #pragma unroll
        for (int mt = 0; mt < 4; ++mt)
            #pragma unroll
            for (int nt = 0; nt < 8; ++nt)
                #pragma unroll
                for (int j = 0; j < 4; ++j) D[mt][nt][j] = 0.f;

        #pragma unroll
        for (int ks = 0; ks < 4; ++ks) {          // K=16 per step
            const int cw = ks * 8;                 // word offset in channel dim
            u32 A[4][4], B[8][2];
            #pragma unroll
            for (int mt = 0; mt < 4; ++mt) {
                int r0 = mbase + mt * 16 + lg;
                int w0 = r0 * HS + cw + lt;
                A[mt][0] = fh_w[w0];
                A[mt][1] = fh_w[w0 + 8 * HS];
                A[mt][2] = fh_w[w0 + 4];
                A[mt][3] = fh_w[w0 + 8 * HS + 4];
            }
            #pragma unroll
            for (int nt = 0; nt < 8; ++nt) {
                int n = nbase + nt * 8 + lg;
                int wb = n * HS + cw + lt;
                B[nt][0] = ekh_w[wb];
                B[nt][1] = ekh_w[wb + 4];
            }
            #pragma unroll
            for (int mt = 0; mt < 4; ++mt)
                #pragma unroll
                for (int nt = 0; nt < 8; ++nt) mma_f16(D[mt][nt], A[mt], B[nt]);
        }

        // Per-row window scan -> exact verify (global codebook) -> packed atomicMin
        #pragma unroll
        for (int mt = 0; mt < 4; ++mt) {
            #pragma unroll
            for (int half = 0; half < 2; ++half) {
                const int r = mbase + mt * 16 + lg + half * 8;
                const float S_r = Sarr[r];
                float dv[16];
                float lm = 3.4e38f;
                #pragma unroll
                for (int nt = 0; nt < 8; ++nt)
                    #pragma unroll
                    for (int j = 0; j < 2; ++j) {
                        int n = nbase + nt * 8 + 2 * lt + j;
                        float d = __fadd_rn(__fmaf_rn(-2.f, D[mt][nt][half * 2 + j], S_r), ee[n]);
                        dv[nt * 2 + j] = d;
                        lm = fminf(lm, d);
                    }
                lm = fminf(lm, __shfl_xor_sync(0xffffffffu, lm, 1));
                lm = fminf(lm, __shfl_xor_sync(0xffffffffu, lm, 2));
                const float thr = lm + 2.f * warr[r];
                #pragma unroll
                for (int q = 0; q < 16; ++q) {
                    if (dv[q] <= thr) {
                        int n = nbase + (q >> 1) * 8 + 2 * lt + (q & 1);
                        // exact re-verify: reference two-rounding chain, e from global
                        const float4* eg = (const float4*)(cb + n * CB_C);
                        float Dx = 0.f;
                        #pragma unroll
                        for (int c4 = 0; c4 < 16; ++c4) {
                            float4 e = __ldg(eg + c4);
                            Dx = __fmaf_rn(fT[(4 * c4 + 0) * FTS + r], e.x, Dx);
                            Dx = __fmaf_rn(fT[(4 * c4 + 1) * FTS + r], e.y, Dx);
                            Dx = __fmaf_rn(fT[(4 * c4 + 2) * FTS + r], e.z, Dx);
                            Dx = __fmaf_rn(fT[(4 * c4 + 3) * FTS + r], e.w, Dx);
                        }
                        float d = __fadd_rn(__fmaf_rn(-2.f, Dx, S_r), ee[n]);
                        u32 b = __float_as_uint(d);
                        u32 mk = (b & 0x80000000u) ? ~b : (b | 0x80000000u);
                        u64 key = ((u64)mk << 32) | (u32)n;
                        atomicMin(&win[r], key);
                    }
                }
            }
        }
    }
    __syncthreads();

    // ---- Outputs + losses (validated machinery) ----
    if (tid < MT) {
        int kf = (int)(win[tid] & 1023u);
        atomicAdd(&hist[kf], 1);
        out[OFF_IDX + (size_t)(tile * MT + tid)] = (float)kf;
    }
    __syncthreads();

    const int p = tid & 127;
    const int chalf = tid >> 7;
    const int kf = (int)(win[p] & 1023u);

    const bool quantz = (plane >= 2);
    float scaleQ = 1.f, invQ = 1.f;
    if (quantz) {
        int lgp = 31 - __clz(plane);
        int kq = 7 - lgp;
        scaleQ = (float)(1 << kq);
        invQ   = 1.f / (float)(1 << kq);
    }
    float acc = 0.f;
    const int c0 = chalf * 32;
    const float* qrow = cb + kf * CB_C;
    #pragma unroll
    for (int c = c0; c < c0 + 32; ++c) {
        float q  = __ldg(qrow + c);
        float xv = fT[c * FTS + p];
        float da = __fsub_rn(q, xv);
        float v  = __fmul_rn(da, da);
        if (quantz) {
            float mm = __fsub_rn(__fmaf_rn(v, scaleQ, 8388608.f), 8388608.f);
            acc = __fmaf_rn(mm, invQ, acc);
        } else acc = __fadd_rn(v, acc);
        out[(size_t)plane * (CB_C * HW) + (size_t)c * HW + pixbase + p] = __fadd_rn(xv, da);
    }
    atomicAdd(&lane_sum[p & 3], acc);
    __syncthreads();
    if (tid < 4) atomicAdd(&g_lane[tid], (double)lane_sum[tid]);
    for (int k = tid; k < CB_K; k += THREADS) {
        int c = hist[k];
        if (c) atomicAdd(&g_counts[k], c);
    }
}

__global__ void vq_finalize(float* __restrict__ out) {
    __shared__ double red[CB_K];
    int t = threadIdx.x;
    int c = g_counts[t];
    double pr = (double)c / (double)N_PIX;
    red[t] = (c > 0) ? (-pr * log2(pr)) : 0.0;
    __syncthreads();
    for (int o = CB_K / 2; o > 0; o >>= 1) {
        if (t < o) red[t] += red[t + o];
        __syncthreads();
    }
    if (t == 0) {
        out[OFF_ENT] = (float)red[0];
        float s0 = (float)g_lane[0], s1 = (float)g_lane[1];
        float s2 = (float)g_lane[2], s3 = (float)g_lane[3];
        float hs = __fadd_rn(__fadd_rn(s0, s1), __fadd_rn(s2, s3));
        float L  = hs * (1.f / 33554432.f);
        out[OFF_LOSS] = __fadd_rn(L, 0.25f * L);
    }
}

extern "C" void kernel_launch(void* const* d_in, const int* in_sizes, int n_in,
                              void* d_out, int out_size) {
    const float* x  = (const float*)d_in[0];
    const float* cb = (const float*)d_in[1];
    float* out = (float*)d_out;
    cudaFuncSetAttribute(vq_mma, cudaFuncAttributeMaxDynamicSharedMemorySize, SMEM_TOTAL);
    vq_zero<<<1, CB_K>>>();
    vq_mma<<<NTILES, THREADS, SMEM_TOTAL>>>(x, cb, out);
    vq_finalize<<<1, CB_K>>>(out);
}

// round 7
// speedup vs baseline: 4.2387x; 4.2387x over previous
#include <cuda_runtime.h>
#include <cstdint>

typedef unsigned long long u64;
typedef unsigned int u32;

// Problem geometry
#define CB_K 512
#define CB_C 64
#define HW   4096
#define N_PIX 524288
#define Q_ELEMS 33554432
#define OFF_IDX  Q_ELEMS
#define OFF_LOSS (OFF_IDX + N_PIX)
#define OFF_ENT  (OFF_LOSS + 1)

#define THREADS 256
#define PIX_PER_CTA 512
#define NBLOCKS 1024

// smem layout (bytes)
#define SB_FT   0                  // fT[c][p]: 64 x 512 f32 = 131072
#define SB_EQ   131072             // eq[g][k]: 16 x 512 u32 (int8x4) = 32768
#define SB_CM   163840             // candidate bitmask: 512 px x 16 u32 = 32768
#define SB_EE   196608             // E_k: 512 f32
#define SB_HIST 198656             // 512 int
#define SB_LANE 200704             // 4 f32
#define SB_EMAX 200720             // 1 int
#define SMEM_TOTAL 200832

#define SE_U 1.5379470e-5f         // (1/512)/127: codebook int8 ulp

__device__ double g_lane[4];
__device__ int    g_counts[CB_K];

__global__ void vq_zero(){
    int t = threadIdx.x;
    if (t < CB_K) g_counts[t] = 0;
    if (t < 4)    g_lane[t] = 0.0;
}

__device__ __forceinline__ void dp4a(int& d, u32 a, u32 b){
    asm("dp4a.s32.s32 %0, %1, %2, %0;" : "+r"(d) : "r"(a), "r"(b));
}

__global__ void __launch_bounds__(THREADS, 1)
vq_dp4a(const float* __restrict__ x, const float* __restrict__ cb, float* __restrict__ out)
{
    extern __shared__ char smem[];
    float* fT   = (float*)(smem + SB_FT);
    u32*   eq   = (u32*)(smem + SB_EQ);
    u32*   cm   = (u32*)(smem + SB_CM);
    float* ee   = (float*)(smem + SB_EE);
    int*   hist = (int*)(smem + SB_HIST);
    float* lane_sum = (float*)(smem + SB_LANE);
    int*   emax_i   = (int*)(smem + SB_EMAX);

    const int tid = threadIdx.x;
    const int plane = blockIdx.x >> 3;
    const int jbase = (blockIdx.x & 7) * PIX_PER_CTA;
    const int p0 = 2 * tid, p1 = p0 + 1;

    for (int i = tid; i < 512 * 16; i += THREADS) cm[i] = 0;
    for (int k = tid; k < CB_K; k += THREADS) hist[k] = 0;
    if (tid < 4)  lane_sum[tid] = 0.f;
    if (tid == 0) *emax_i = 0;

    // Stage x tile (coalesced)
    const float* xin = x + (size_t)plane * (CB_C * HW) + jbase;
    for (int i = tid; i < CB_C * PIX_PER_CTA / 4; i += THREADS) {
        int c = i >> 7, p4 = i & 127;
        *(float4*)(fT + c * 512 + 4 * p4) = *(const float4*)(xin + (size_t)c * HW + 4 * p4);
    }
    // Codebook: E_k exact (sequential fma, ascending c) + int8 pack (lane-per-code: STS conflict-free)
    for (int k = tid; k < CB_K; k += THREADS) {
        const float4* eg = (const float4*)(cb + k * CB_C);
        float s = 0.f;
        #pragma unroll
        for (int g = 0; g < 16; ++g) {
            float4 e = __ldg(eg + g);
            s = __fmaf_rn(e.x, e.x, s); s = __fmaf_rn(e.y, e.y, s);
            s = __fmaf_rn(e.z, e.z, s); s = __fmaf_rn(e.w, e.w, s);
            int q0 = __float2int_rn(e.x * 65024.f);
            int q1 = __float2int_rn(e.y * 65024.f);
            int q2 = __float2int_rn(e.z * 65024.f);
            int q3 = __float2int_rn(e.w * 65024.f);
            eq[g * 512 + k] = (u32)(q0 & 255) | ((u32)(q1 & 255) << 8)
                            | ((u32)(q2 & 255) << 16) | ((u32)(q3 & 255) << 24);
        }
        ee[k] = s;
        atomicMax(emax_i, __float_as_int(s));   // positive: int order == float order
    }
    __syncthreads();

    // Per-pixel S (exact chain), fmax, int8 pack of f
    float S0 = 0.f, S1 = 0.f, fx0 = 0.f, fx1 = 0.f;
    for (int c = 0; c < CB_C; ++c) {
        float2 v = *(const float2*)(fT + c * 512 + p0);
        S0 = __fmaf_rn(v.x, v.x, S0); S1 = __fmaf_rn(v.y, v.y, S1);
        fx0 = fmaxf(fx0, fabsf(v.x)); fx1 = fmaxf(fx1, fabsf(v.y));
    }
    const float inv0 = fx0 > 0.f ? 127.f / fx0 : 0.f;
    const float inv1 = fx1 > 0.f ? 127.f / fx1 : 0.f;
    u32 fq0[16], fq1[16];
    #pragma unroll
    for (int g = 0; g < 16; ++g) {
        u32 a0 = 0, a1 = 0;
        #pragma unroll
        for (int u = 0; u < 4; ++u) {
            float2 v = *(const float2*)(fT + (4 * g + u) * 512 + p0);
            int q0 = __float2int_rn(v.x * inv0);
            int q1 = __float2int_rn(v.y * inv1);
            a0 |= (u32)(q0 & 255) << (8 * u);
            a1 |= (u32)(q1 & 255) << (8 * u);
        }
        fq0[g] = a0; fq1[g] = a1;
    }
    const float Emax = __int_as_float(*emax_i);
    const float sqE  = __fsqrt_rn(Emax);
    // Sound window (x1.5 margin): |d'-d| <= de*8*sqrtS + df*(8*sqrtEmax + 64*de) + fp slack
    const float W0 = 3.f * (__fmaf_rn(6.152e-5f, __fsqrt_rn(S0), 4e-5f)
                            + (fx0 * (1.f/254.f)) * __fmaf_rn(8.f, sqE, 4.92e-4f));
    const float W1 = 3.f * (__fmaf_rn(6.152e-5f, __fsqrt_rn(S1), 4e-5f)
                            + (fx1 * (1.f/254.f)) * __fmaf_rn(8.f, sqE, 4.92e-4f));
    const float c20 = -fx0 * 2.4218754e-7f;   // -2*(fmax/127)*SE_U
    const float c21 = -fx1 * 2.4218754e-7f;

    // ---- dp4a screen: 512 codes, streaming min + candidate bits ----
    float mm0 = 3.4e38f, mm1 = 3.4e38f;
    u32 cw0 = 0, cw1 = 0;
    #pragma unroll 1
    for (int kt = 0; kt < 64; ++kt) {
        int D0[8] = {0,0,0,0,0,0,0,0}, D1[8] = {0,0,0,0,0,0,0,0};
        #pragma unroll
        for (int g = 0; g < 16; ++g) {
            const u32* ep = eq + g * 512 + kt * 8;
            uint4 ea = *(const uint4*)ep;
            uint4 eb = *(const uint4*)(ep + 4);
            dp4a(D0[0], fq0[g], ea.x); dp4a(D1[0], fq1[g], ea.x);
            dp4a(D0[1], fq0[g], ea.y); dp4a(D1[1], fq1[g], ea.y);
            dp4a(D0[2], fq0[g], ea.z); dp4a(D1[2], fq1[g], ea.z);
            dp4a(D0[3], fq0[g], ea.w); dp4a(D1[3], fq1[g], ea.w);
            dp4a(D0[4], fq0[g], eb.x); dp4a(D1[4], fq1[g], eb.x);
            dp4a(D0[5], fq0[g], eb.y); dp4a(D1[5], fq1[g], eb.y);
            dp4a(D0[6], fq0[g], eb.z); dp4a(D1[6], fq1[g], eb.z);
            dp4a(D0[7], fq0[g], eb.w); dp4a(D1[7], fq1[g], eb.w);
        }
        const float* eep = ee + kt * 8;
        float4 Ea = *(const float4*)eep;
        float4 Eb = *(const float4*)(eep + 4);
        float E[8] = {Ea.x, Ea.y, Ea.z, Ea.w, Eb.x, Eb.y, Eb.z, Eb.w};
        #pragma unroll
        for (int j = 0; j < 8; ++j) {
            float d0 = __fmaf_rn(c20, __int2float_rn(D0[j]), __fadd_rn(S0, E[j]));
            float d1 = __fmaf_rn(c21, __int2float_rn(D1[j]), __fadd_rn(S1, E[j]));
            u32 bit = 1u << ((kt & 3) * 8 + j);
            if (d0 <= mm0 + W0) cw0 |= bit;
            if (d1 <= mm1 + W1) cw1 |= bit;
            mm0 = fminf(mm0, d0); mm1 = fminf(mm1, d1);
        }
        if ((kt & 3) == 3) {
            int w = kt >> 2;
            if (cw0) cm[p0 * 16 + w] = cw0;
            if (cw1) cm[p1 * 16 + w] = cw1;
            cw0 = 0; cw1 = 0;
        }
    }

    // ---- exact verification (reference two-rounding chain), ascending k ----
    float bd0 = 3.4e38f, bd1 = 3.4e38f;
    int bk0 = 0, bk1 = 0;
    #pragma unroll 1
    for (int w = 0; w < 16; ++w) {
        u32 bits0 = cm[p0 * 16 + w];
        while (bits0) {
            int j = __ffs(bits0) - 1; bits0 &= bits0 - 1;
            int k = w * 32 + j;
            const float4* eg = (const float4*)(cb + k * CB_C);
            float Dx = 0.f;
            #pragma unroll
            for (int c4 = 0; c4 < 16; ++c4) {
                float4 e = __ldg(eg + c4);
                Dx = __fmaf_rn(fT[(4*c4+0) * 512 + p0], e.x, Dx);
                Dx = __fmaf_rn(fT[(4*c4+1) * 512 + p0], e.y, Dx);
                Dx = __fmaf_rn(fT[(4*c4+2) * 512 + p0], e.z, Dx);
                Dx = __fmaf_rn(fT[(4*c4+3) * 512 + p0], e.w, Dx);
            }
            float d = __fadd_rn(__fmaf_rn(-2.f, Dx, S0), ee[k]);
            if (d < bd0) { bd0 = d; bk0 = k; }
        }
        u32 bits1 = cm[p1 * 16 + w];
        while (bits1) {
            int j = __ffs(bits1) - 1; bits1 &= bits1 - 1;
            int k = w * 32 + j;
            const float4* eg = (const float4*)(cb + k * CB_C);
            float Dx = 0.f;
            #pragma unroll
            for (int c4 = 0; c4 < 16; ++c4) {
                float4 e = __ldg(eg + c4);
                Dx = __fmaf_rn(fT[(4*c4+0) * 512 + p1], e.x, Dx);
                Dx = __fmaf_rn(fT[(4*c4+1) * 512 + p1], e.y, Dx);
                Dx = __fmaf_rn(fT[(4*c4+2) * 512 + p1], e.z, Dx);
                Dx = __fmaf_rn(fT[(4*c4+3) * 512 + p1], e.w, Dx);
            }
            float d = __fadd_rn(__fmaf_rn(-2.f, Dx, S1), ee[k]);
            if (d < bd1) { bd1 = d; bk1 = k; }
        }
    }

    // ---- outputs + losses (R3-validated machinery) ----
    atomicAdd(&hist[bk0], 1);
    atomicAdd(&hist[bk1], 1);
    {
        size_t pix = (size_t)plane * HW + jbase + p0;
        *(float2*)(out + OFF_IDX + pix) = make_float2((float)bk0, (float)bk1);
    }

    const bool quantz = (plane >= 2);
    float scaleQ = 1.f, invQ = 1.f;
    if (quantz) {
        int lgp = 31 - __clz(plane);
        int kq = 7 - lgp;
        scaleQ = (float)(1 << kq);
        invQ   = 1.f / (float)(1 << kq);
    }
    float acc0 = 0.f, acc1 = 0.f;
    float* outq = out + (size_t)plane * (CB_C * HW) + jbase + p0;
    const float* q0r = cb + bk0 * CB_C;
    const float* q1r = cb + bk1 * CB_C;
    #pragma unroll 4
    for (int c = 0; c < CB_C; ++c) {
        float q0 = __ldg(q0r + c), q1 = __ldg(q1r + c);
        float2 v = *(const float2*)(fT + c * 512 + p0);
        float da = __fsub_rn(q0, v.x), db = __fsub_rn(q1, v.y);
        float v0 = __fmul_rn(da, da), v1 = __fmul_rn(db, db);
        if (quantz) {
            float m0 = __fsub_rn(__fmaf_rn(v0, scaleQ, 8388608.f), 8388608.f);
            float m1 = __fsub_rn(__fmaf_rn(v1, scaleQ, 8388608.f), 8388608.f);
            acc0 = __fmaf_rn(m0, invQ, acc0);
            acc1 = __fmaf_rn(m1, invQ, acc1);
        } else {
            acc0 = __fadd_rn(v0, acc0);
            acc1 = __fadd_rn(v1, acc1);
        }
        *(float2*)(outq + (size_t)c * HW) = make_float2(__fadd_rn(v.x, da), __fadd_rn(v.y, db));
    }
    atomicAdd(&lane_sum[p0 & 3], acc0);
    atomicAdd(&lane_sum[(p0 & 3) + 1], acc1);
    __syncthreads();
    if (tid < 4) atomicAdd(&g_lane[tid], (double)lane_sum[tid]);
    for (int k = tid; k < CB_K; k += THREADS) {
        int c = hist[k];
        if (c) atomicAdd(&g_counts[k], c);
    }
}

__global__ void vq_finalize(float* __restrict__ out) {
    __shared__ double red[CB_K];
    int t = threadIdx.x;
    int c = g_counts[t];
    double pr = (double)c / (double)N_PIX;
    red[t] = (c > 0) ? (-pr * log2(pr)) : 0.0;
    __syncthreads();
    for (int o = CB_K / 2; o > 0; o >>= 1) {
        if (t < o) red[t] += red[t + o];
        __syncthreads();
    }
    if (t == 0) {
        out[OFF_ENT] = (float)red[0];
        float s0 = (float)g_lane[0], s1 = (float)g_lane[1];
        float s2 = (float)g_lane[2], s3 = (float)g_lane[3];
        float hs = __fadd_rn(__fadd_rn(s0, s1), __fadd_rn(s2, s3));
        float L  = hs * (1.f / 33554432.f);
        out[OFF_LOSS] = __fadd_rn(L, 0.25f * L);
    }
}

extern "C" void kernel_launch(void* const* d_in, const int* in_sizes, int n_in,
                              void* d_out, int out_size) {
    const float* x  = (const float*)d_in[0];
    const float* cb = (const float*)d_in[1];
    float* out = (float*)d_out;
    cudaFuncSetAttribute(vq_dp4a, cudaFuncAttributeMaxDynamicSharedMemorySize, SMEM_TOTAL);
    vq_zero<<<1, CB_K>>>();
    vq_dp4a<<<NBLOCKS, THREADS, SMEM_TOTAL>>>(x, cb, out);
    vq_finalize<<<1, CB_K>>>(out);
}

// round 8
// speedup vs baseline: 4.3181x; 1.0187x over previous
#include <cuda_runtime.h>
#include <cstdint>

// Problem geometry
#define CB_K 512
#define CB_C 64
#define HW   4096                     // 64*64 pixels per (b,t) plane
#define NPLANES 128                   // B*T
#define N_PIX  (NPLANES * HW)         // 524288
#define Q_ELEMS (N_PIX * CB_C)        // 33554432
#define OFF_IDX  Q_ELEMS
#define OFF_LOSS (OFF_IDX + N_PIX)
#define OFF_ENT  (OFF_LOSS + 1)

// Kernel config: 512 threads, 1 pixel/thread, 512 px/CTA
#define THREADS 512
#define PIX_PER_CTA 512
#define NBLOCKS (N_PIX / PIX_PER_CTA) // 1024
#define ESTRIDE 516                   // padded floats per channel row of codebook
#define SMEM_FLOATS (CB_C * ESTRIDE)  // 33024 floats
#define SMEM_BYTES (SMEM_FLOATS*4 + CB_K*4 /*E*/ + CB_K*4 /*hist*/ + 4*4 /*lane_sum*/)

typedef unsigned long long u64;

__device__ double g_lane[4];          // per-(index mod 4) loss lane sums (XLA vec4 emulation)
__device__ int    g_counts[CB_K];

__global__ void vq_zero() {
    int t = threadIdx.x;
    if (t < CB_K) g_counts[t] = 0;
    if (t < 4)    g_lane[t] = 0.0;
}

__global__ void __launch_bounds__(THREADS, 1)
vq_main(const float* __restrict__ x, const float* __restrict__ cb, float* __restrict__ out) {
    extern __shared__ float smem[];
    float* es   = smem;                       // codebook transposed [c][k], padded stride 516
    float* ee   = smem + SMEM_FLOATS;         // E_k = sum_c e_{k,c}^2 (fp32 sequential fma)
    int*   hist = (int*)(ee + CB_K);          // per-CTA histogram
    float* lane_sum = (float*)(hist + CB_K);  // per-CTA loss partials, by (index mod 4)

    const int tid = threadIdx.x;

    // Stage codebook transposed (coalesced reads)
    for (int i = tid; i < CB_K * CB_C; i += THREADS) {
        int k = i >> 6, c = i & 63;
        es[c * ESTRIDE + k] = cb[i];
    }
    for (int k = tid; k < CB_K; k += THREADS) hist[k] = 0;
    if (tid < 4) lane_sum[tid] = 0.f;
    __syncthreads();
    // E_k = sum_c e^2, sequential fma ascending c (reference chain)
    for (int k = tid; k < CB_K; k += THREADS) {
        float s = 0.f;
        #pragma unroll
        for (int c = 0; c < CB_C; ++c) { float e = es[c * ESTRIDE + k]; s = __fmaf_rn(e, e, s); }
        ee[k] = s;
    }
    __syncthreads();

    // One pixel per thread; all 64 channels in registers (x read once, coalesced).
    const int plane = blockIdx.x >> 3;
    const int j = ((blockIdx.x & 7) * PIX_PER_CTA) + tid;
    const float* xp = x + (size_t)plane * (CB_C * HW) + j;

    float f[CB_C];
    #pragma unroll
    for (int c = 0; c < CB_C; ++c) f[c] = xp[(size_t)c * HW];

    // S = sum_c f_c^2, sequential fma ascending c
    float S = 0.f;
    #pragma unroll
    for (int c = 0; c < CB_C; ++c) S = __fmaf_rn(f[c], f[c], S);

    unsigned sbase = (unsigned)__cvta_generic_to_shared(es);
    unsigned hbase = (unsigned)__cvta_generic_to_shared(ee);

    float best = 3.4e38f;
    int bi = 0;

    // 32 tiles of 16 codes. Raw dot D in packed f32x2 (each lane = sequential fp32
    // fma over ascending c), then the reference two-rounding chain:
    //   t = fl(S - 2*D); d = fl(t + E_k); argmin ascending k, strict <.
    #pragma unroll 1
    for (int kt = 0; kt < CB_K / 16; ++kt) {
        u64 a[8] = {0,0,0,0,0,0,0,0};
        unsigned ebase = sbase + (unsigned)(kt * 64);
        #pragma unroll
        for (int c = 0; c < CB_C; ++c) {
            u64 e0, e1, e2, e3, e4, e5, e6, e7;
            unsigned ea = ebase + (unsigned)(c * (ESTRIDE * 4));
            asm volatile("ld.shared.v2.u64 {%0,%1}, [%2];"    : "=l"(e0), "=l"(e1) : "r"(ea));
            asm volatile("ld.shared.v2.u64 {%0,%1}, [%2+16];" : "=l"(e2), "=l"(e3) : "r"(ea));
            asm volatile("ld.shared.v2.u64 {%0,%1}, [%2+32];" : "=l"(e4), "=l"(e5) : "r"(ea));
            asm volatile("ld.shared.v2.u64 {%0,%1}, [%2+48];" : "=l"(e6), "=l"(e7) : "r"(ea));
            u64 fd;
            asm("mov.b64 %0, {%1,%1};" : "=l"(fd) : "f"(f[c]));
            asm("fma.rn.f32x2 %0, %1, %2, %0;" : "+l"(a[0]) : "l"(fd), "l"(e0));
            asm("fma.rn.f32x2 %0, %1, %2, %0;" : "+l"(a[1]) : "l"(fd), "l"(e1));
            asm("fma.rn.f32x2 %0, %1, %2, %0;" : "+l"(a[2]) : "l"(fd), "l"(e2));
            asm("fma.rn.f32x2 %0, %1, %2, %0;" : "+l"(a[3]) : "l"(fd), "l"(e3));
            asm("fma.rn.f32x2 %0, %1, %2, %0;" : "+l"(a[4]) : "l"(fd), "l"(e4));
            asm("fma.rn.f32x2 %0, %1, %2, %0;" : "+l"(a[5]) : "l"(fd), "l"(e5));
            asm("fma.rn.f32x2 %0, %1, %2, %0;" : "+l"(a[6]) : "l"(fd), "l"(e6));
            asm("fma.rn.f32x2 %0, %1, %2, %0;" : "+l"(a[7]) : "l"(fd), "l"(e7));
        }
        // Epilogue: E for these 16 codes, two reference roundings, streaming argmin.
        u64 h[8];
        {
            unsigned ha = hbase + (unsigned)(kt * 64);
            asm volatile("ld.shared.v2.u64 {%0,%1}, [%2];"    : "=l"(h[0]), "=l"(h[1]) : "r"(ha));
            asm volatile("ld.shared.v2.u64 {%0,%1}, [%2+16];" : "=l"(h[2]), "=l"(h[3]) : "r"(ha));
            asm volatile("ld.shared.v2.u64 {%0,%1}, [%2+32];" : "=l"(h[4]), "=l"(h[5]) : "r"(ha));
            asm volatile("ld.shared.v2.u64 {%0,%1}, [%2+48];" : "=l"(h[6]), "=l"(h[7]) : "r"(ha));
        }
        #pragma unroll
        for (int q = 0; q < 8; ++q) {
            float elo = __uint_as_float((unsigned)h[q]);
            float ehi = __uint_as_float((unsigned)(h[q] >> 32));
            float Dlo = __uint_as_float((unsigned)a[q]);
            float Dhi = __uint_as_float((unsigned)(a[q] >> 32));
            float dlo = __fadd_rn(__fmaf_rn(-2.f, Dlo, S), elo);
            float dhi = __fadd_rn(__fmaf_rn(-2.f, Dhi, S), ehi);
            int k0 = kt * 16 + 2 * q;
            if (dlo < best) { best = dlo; bi = k0;     }
            if (dhi < best) { best = dhi; bi = k0 + 1; }
        }
    }

    // Histogram (shared)
    atomicAdd(&hist[bi], 1);

    // ---- Loss: XLA CPU single-NEON-vec4 fp32 reduction emulation (validated R3) ----
    const bool quant = (plane >= 2);
    float scaleQ = 1.f, invQ = 1.f;
    if (quant) {
        int lg = 31 - __clz(plane);          // 1..6
        int kq = 7 - lg;                     // 6..1
        scaleQ = (float)(1 << kq);
        invQ   = 1.f / (float)(1 << kq);
    }

    float acc = 0.f;
    float* outq = out + (size_t)plane * (CB_C * HW) + j;
    #pragma unroll
    for (int c = 0; c < CB_C; ++c) {
        float q  = es[c * ESTRIDE + bi];
        float da = __fsub_rn(q, f[c]);
        float v  = __fmul_rn(da, da);
        if (quant) {
            float mm = __fsub_rn(__fmaf_rn(v, scaleQ, 8388608.f), 8388608.f); // rtn_even(v*2^k)
            acc = __fmaf_rn(mm, invQ, acc);   // exact: multiples of u
        } else {
            acc = __fadd_rn(v, acc);
        }
        outq[(size_t)c * HW] = __fadd_rn(f[c], da);   // quantized_st = fl(x + fl(q-x))
    }
    out[OFF_IDX + (size_t)plane * HW + j] = (float)bi;

    // CTA-level per-lane reduce (fp32 shared atomics exact: multiples of u, bounded),
    // then one double atomic per lane per CTA.
    atomicAdd(&lane_sum[j & 3], acc);
    __syncthreads();
    if (tid < 4) atomicAdd(&g_lane[tid], (double)lane_sum[tid]);

    // Histogram flush
    for (int k = tid; k < CB_K; k += THREADS) {
        int cth = hist[k];
        if (cth) atomicAdd(&g_counts[k], cth);
    }
}

__global__ void vq_finalize(float* __restrict__ out) {
    __shared__ double red[CB_K];
    int t = threadIdx.x;
    int c = g_counts[t];
    double p = (double)c / (double)N_PIX;
    red[t] = (c > 0) ? (-p * log2(p)) : 0.0;
    __syncthreads();
    for (int o = CB_K / 2; o > 0; o >>= 1) {
        if (t < o) red[t] += red[t + o];
        __syncthreads();
    }
    if (t == 0) {
        out[OFF_ENT] = (float)red[0];
        // NEON faddp horizontal reduce: (s0+s1) + (s2+s3), all fp32.
        float s0 = (float)g_lane[0], s1 = (float)g_lane[1];
        float s2 = (float)g_lane[2], s3 = (float)g_lane[3];
        float hs = __fadd_rn(__fadd_rn(s0, s1), __fadd_rn(s2, s3));
        float L  = hs * (1.f / 33554432.f);        // exact power-of-2 scale
        out[OFF_LOSS] = __fadd_rn(L, 0.25f * L);   // vq = L + 0.25*L
    }
}

extern "C" void kernel_launch(void* const* d_in, const int* in_sizes, int n_in,
                              void* d_out, int out_size) {
    const float* x  = (const float*)d_in[0];
    const float* cb = (const float*)d_in[1];
    float* out = (float*)d_out;
    cudaFuncSetAttribute(vq_main, cudaFuncAttributeMaxDynamicSharedMemorySize, SMEM_BYTES);
    vq_zero<<<1, CB_K>>>();
    vq_main<<<NBLOCKS, THREADS, SMEM_BYTES>>>(x, cb, out);
    vq_finalize<<<1, CB_K>>>(out);
}